// round 1
// baseline (speedup 1.0000x reference)
#include <cuda_runtime.h>

#define N_ANCH 262144
#define N_CLS 80
#define KTOP 1024
#define CAP 4096
#define FULLM 0xffffffffu

// ---------------- device scratch (no allocations allowed) ----------------
__device__ unsigned            g_key[N_ANCH];     // monotone key of masked conf
__device__ unsigned char       g_label[N_ANCH];   // argmax class
__device__ unsigned            g_hist[3][2048];
__device__ unsigned            g_done[3];
__device__ unsigned            g_sel1, g_sel2;
__device__ unsigned            g_need, g_thresh;
__device__ unsigned            g_ncand;
__device__ unsigned long long  g_cand[CAP];
__device__ unsigned long long  g_sorted[KTOP];
__device__ float4              g_box[KTOP];
__device__ float4              g_obox[KTOP];
__device__ float               g_conf[KTOP];
__device__ float               g_labf[KTOP];
__device__ unsigned            g_mask[KTOP * 32];

__device__ __forceinline__ unsigned fkey(float f) {
    unsigned u = __float_as_uint(f);
    return (u & 0x80000000u) ? ~u : (u | 0x80000000u);
}

// ---------------- kernel 1: per-anchor max/argmax over 80 classes ----------------
// One warp per anchor. Scores >= 0 so uint-bit comparison == float comparison.
// Argmax tie-break: first (lowest) class index, matching jnp.argmax.
__global__ void conf_kernel(const float* __restrict__ scores) {
    int tid = threadIdx.x;
    if (blockIdx.x == 0) {  // per-launch scratch reset (graph replays!)
        for (int i = tid; i < 3 * 2048; i += blockDim.x) ((unsigned*)g_hist)[i] = 0u;
        if (tid < 3) g_done[tid] = 0u;
        if (tid == 0) { g_ncand = 0u; g_need = KTOP; }
    }
    int lane = tid & 31;
    int n = (int)((blockIdx.x * blockDim.x + tid) >> 5);
    if (n >= N_ANCH) return;
    const float* p = scores + (size_t)n * N_CLS;
    unsigned b0 = __float_as_uint(p[lane]);
    unsigned b1 = __float_as_uint(p[lane + 32]);
    unsigned b2 = (lane < 16) ? __float_as_uint(p[64 + lane]) : 0u;
    unsigned loc = max(b0, max(b1, b2));
    unsigned vmax = __reduce_max_sync(FULLM, loc);
    unsigned m0 = __ballot_sync(FULLM, b0 == vmax);
    int label;
    if (m0) label = __ffs(m0) - 1;
    else {
        unsigned m1 = __ballot_sync(FULLM, b1 == vmax);
        if (m1) label = 32 + __ffs(m1) - 1;
        else {
            unsigned m2 = __ballot_sync(FULLM, (lane < 16) && (b2 == vmax));
            label = 64 + __ffs(m2) - 1;
        }
    }
    if (lane == 0) {
        float conf = __uint_as_float(vmax);
        float mk = (conf >= 0.5f) ? conf : -1.0f;   // masked_conf
        g_key[n] = fkey(mk);
        g_label[n] = (unsigned char)label;
    }
}

// ---------------- kernels 2-4: radix-select passes (hist + fused last-block scan) ----
// digits: pass0 = bits[31:21], pass1 = bits[20:10], pass2 = bits[9:0]
__global__ void hist_scan_kernel(int pass) {
    __shared__ unsigned sa[2048];
    __shared__ unsigned sb[2048];
    __shared__ int lastFlag;
    int tid = threadIdx.x;
    for (int i = tid; i < 2048; i += blockDim.x) sa[i] = 0u;
    __syncthreads();
    unsigned sel1 = g_sel1, sel2 = g_sel2;   // valid for pass>0 (written by prior pass)
    int stride = gridDim.x * blockDim.x;
    for (int n = blockIdx.x * blockDim.x + tid; n < N_ANCH; n += stride) {
        unsigned k = g_key[n];
        if (pass == 0)      atomicAdd(&sa[k >> 21], 1u);
        else if (pass == 1) { if ((k >> 21) == sel1) atomicAdd(&sa[(k >> 10) & 2047u], 1u); }
        else                { if ((k >> 10) == ((sel1 << 11) | sel2)) atomicAdd(&sa[k & 1023u], 1u); }
    }
    __syncthreads();
    for (int i = tid; i < 2048; i += blockDim.x)
        if (sa[i]) atomicAdd(&g_hist[pass][i], sa[i]);
    __threadfence();
    if (tid == 0) lastFlag = (atomicAdd(&g_done[pass], 1u) == (unsigned)(gridDim.x - 1));
    __syncthreads();
    if (!lastFlag) return;

    // ---- last block: suffix-sum scan over bins, pick threshold digit ----
    int NB = (pass == 2) ? 1024 : 2048;
    for (int i = tid; i < 2048; i += blockDim.x) sa[i] = (i < NB) ? g_hist[pass][i] : 0u;
    __syncthreads();
    unsigned* a = sa; unsigned* b = sb;
    for (int off = 1; off < 2048; off <<= 1) {
        for (int i = tid; i < 2048; i += blockDim.x)
            b[i] = a[i] + ((i + off < 2048) ? a[i + off] : 0u);
        __syncthreads();
        unsigned* t = a; a = b; b = t;
    }
    unsigned need = g_need;
    for (int i = tid; i < NB; i += blockDim.x) {
        unsigned Sincl = a[i];
        unsigned Sx = (i + 1 < 2048) ? a[i + 1] : 0u;   // count strictly above bin i
        if (Sx < need && need <= Sincl) {                // unique winner bin
            if (pass == 0)      g_sel1 = (unsigned)i;
            else if (pass == 1) g_sel2 = (unsigned)i;
            else                g_thresh = (sel1 << 21) | (sel2 << 10) | (unsigned)i;
            g_need = need - Sx;
        }
    }
}

// ---------------- kernel 5: compact candidates with key >= threshold ----------------
__global__ void compact_kernel() {
    unsigned T = g_thresh;
    int stride = gridDim.x * blockDim.x;
    for (int n = blockIdx.x * blockDim.x + threadIdx.x; n < N_ANCH; n += stride) {
        unsigned k = g_key[n];
        if (k >= T) {
            unsigned pos = atomicAdd(&g_ncand, 1u);
            if (pos < CAP)
                g_cand[pos] = (((unsigned long long)k) << 32) | (unsigned)(~(unsigned)n);
        }
    }
}

// ---------------- kernel 6: exact ranks by brute force -> sorted scatter ----------------
// Keys are unique (embedded ~idx), so ranks 0..nc-1 are a permutation; rank<1024 wins.
// Ordering (key desc, idx asc) == jax.lax.top_k tie-break (lower index first).
__global__ void rank_kernel() {
    __shared__ unsigned long long buf[1024];
    unsigned nc = min(g_ncand, (unsigned)CAP);
    int i = blockIdx.x * blockDim.x + threadIdx.x;
    unsigned long long my = (i < (int)nc) ? g_cand[i] : 0ull;
    unsigned r = 0;
    for (unsigned base = 0; base < nc; base += 1024u) {
        unsigned len = min(1024u, nc - base);
        __syncthreads();
        for (unsigned j = threadIdx.x; j < len; j += blockDim.x) buf[j] = g_cand[base + j];
        __syncthreads();
        for (unsigned j = 0; j < len; j++) r += (buf[j] > my) ? 1u : 0u;
    }
    if (i < (int)nc && r < KTOP) g_sorted[r] = my;
}

// ---------------- kernel 7: gather boxes, max_coord, offset boxes ----------------
__global__ void prep_kernel(const float* __restrict__ boxes) {
    int r = threadIdx.x;
    unsigned long long s = g_sorted[r];
    unsigned idx = ~(unsigned)(s & 0xffffffffull);
    unsigned key = (unsigned)(s >> 32);
    unsigned fb = (key & 0x80000000u) ? (key & 0x7fffffffu) : ~key;
    float conf = __uint_as_float(fb);
    float4 bx = __ldg((const float4*)boxes + idx);
    unsigned lab = (unsigned)g_label[idx];

    float m = fmaxf(fmaxf(bx.x, bx.y), fmaxf(bx.z, bx.w));
    __shared__ float red[32];
    __shared__ float mc_sh;
    for (int o = 16; o; o >>= 1) m = fmaxf(m, __shfl_xor_sync(FULLM, m, o));
    if ((r & 31) == 0) red[r >> 5] = m;
    __syncthreads();
    if (r < 32) {
        float v = red[r];
        for (int o = 16; o; o >>= 1) v = fmaxf(v, __shfl_xor_sync(FULLM, v, o));
        if (r == 0) mc_sh = v + 1.0f;     // max_coord = max(top_boxes) + 1
    }
    __syncthreads();
    float off = (float)lab * mc_sh;       // same op order as reference
    g_box[r] = bx;
    g_obox[r] = make_float4(bx.x + off, bx.y + off, bx.z + off, bx.w + off);
    g_conf[r] = conf;
    g_labf[r] = (float)lab;
}

// ---------------- kernel 8: suppression bitmask (1024x1024 upper triangle) ----------------
__global__ void mask_kernel() {
    int row = blockIdx.x * 8 + (threadIdx.x >> 5);
    int lane = threadIdx.x & 31;
    float4 bi = g_obox[row];
    float ai = (bi.z - bi.x) * (bi.w - bi.y);
#pragma unroll 4
    for (int it = 0; it < 32; it++) {
        int j = it * 32 + lane;
        float4 bj = g_obox[j];
        float aj = (bj.z - bj.x) * (bj.w - bj.y);
        float lx = fmaxf(bi.x, bj.x);
        float ly = fmaxf(bi.y, bj.y);
        float rx = fminf(bi.z, bj.z);
        float ry = fminf(bi.w, bj.w);
        float w = fmaxf(rx - lx, 0.0f);
        float h = fmaxf(ry - ly, 0.0f);
        float inter = w * h;
        float uni = ai + aj - inter;
        float iou = inter / fmaxf(uni, 1e-9f);
        bool sup = (iou > 0.6f) && (j > row);
        unsigned bal = __ballot_sync(FULLM, sup);
        if (lane == 0) g_mask[row * 32 + it] = bal;
    }
}

// ---------------- kernel 9: sparse greedy NMS reduce + masked output ----------------
// Greedy keep is the unique solution of keep[i] = valid[i] && !exists j<i (keep[j] && iou>thr).
// Rows whose mask row is all-zero never change keep -> process only nonzero rows, in order.
__global__ void final_kernel(float* __restrict__ out) {
    __shared__ unsigned keepw[32];
    __shared__ unsigned nzm[32];
    __shared__ unsigned short list[1024];
    __shared__ int Lsh;
    int tid = threadIdx.x;
    int warp = tid >> 5, lane = tid & 31;

    float conf = g_conf[tid];
    unsigned vb = __ballot_sync(FULLM, conf >= 0.5f);   // valid
    if (lane == 0) keepw[warp] = vb;

    // per-row nonzero flags: warp w scans rows [32w, 32w+32), coalesced word reads
    unsigned nzbits = 0;
    for (int k2 = 0; k2 < 32; k2++) {
        unsigned wv = g_mask[(warp * 32 + k2) * 32 + lane];
        if (__ballot_sync(FULLM, wv != 0u)) nzbits |= (1u << k2);
    }
    if (lane == 0) nzm[warp] = nzbits;
    __syncthreads();

    if (tid == 0) {   // ascending ordered list of nonzero rows
        int L = 0;
        for (int w = 0; w < 32; w++) {
            unsigned m = nzm[w];
            while (m) { int b = __ffs(m) - 1; list[L++] = (unsigned short)(w * 32 + b); m &= m - 1; }
        }
        Lsh = L;
    }
    __syncthreads();

    if (warp == 0) {  // serial greedy over the (short) nonzero-row list
        unsigned kw = keepw[lane];
        int L = Lsh;
        for (int t = 0; t < L; t++) {
            int i = list[t];
            unsigned ow = __shfl_sync(FULLM, kw, i >> 5);
            if ((ow >> (i & 31)) & 1u) kw &= ~g_mask[i * 32 + lane];
        }
        keepw[lane] = kw;
    }
    __syncthreads();

    bool kp = (keepw[warp] >> lane) & 1u;
    float4 b = g_box[tid];
    float lf = g_labf[tid];
    float* o = out + tid * 6;
    if (kp) { o[0] = b.x; o[1] = b.y; o[2] = b.z; o[3] = b.w; o[4] = conf; o[5] = lf; }
    else    { o[0] = 0.f; o[1] = 0.f; o[2] = 0.f; o[3] = 0.f; o[4] = 0.f; o[5] = 0.f; }
}

// ---------------- launch ----------------
extern "C" void kernel_launch(void* const* d_in, const int* in_sizes, int n_in,
                              void* d_out, int out_size) {
    const float* boxes  = (const float*)d_in[0];
    const float* scores = (const float*)d_in[1];
    // identify by size in case of metadata order surprises
    if (n_in >= 2 && in_sizes[0] > in_sizes[1]) { const float* t = boxes; boxes = scores; scores = t; }

    conf_kernel<<<N_ANCH / 8, 256>>>(scores);   // 1 warp/anchor, 8 anchors/block
    hist_scan_kernel<<<128, 256>>>(0);
    hist_scan_kernel<<<128, 256>>>(1);
    hist_scan_kernel<<<128, 256>>>(2);
    compact_kernel<<<128, 256>>>();
    rank_kernel<<<32, 128>>>();
    prep_kernel<<<1, 1024>>>(boxes);
    mask_kernel<<<128, 256>>>();
    final_kernel<<<1, 1024>>>((float*)d_out);
}